// round 15
// baseline (speedup 1.0000x reference)
#include <cuda_runtime.h>
#include <cuda_fp16.h>
#include <cstdint>

#define NB 8
#define NL 4096
#define ND 1024
#define NM1 (NB*NL)      // 32768
#define NM4 (NM1/4)      // 8192
#define NM16 (NM1/16)    // 2048

// ---------------- static device scratch ----------------
__device__ __half g_xh[(size_t)NM1*ND];     // clipped x, fp16 (64 MiB)
__device__ __half g_m4h[(size_t)NM4*ND];    // group-4 means, fp16
__device__ __half g_m16h[(size_t)NM16*ND];  // group-16 means, fp16
__device__ __half g_W1h[(size_t)ND*ND];
__device__ __half g_W4h[(size_t)ND*ND];
__device__ __half g_W16h[(size_t)ND*ND];
__device__ float  g_logitsP[(size_t)8*NM1*2];  // per-nb logit slabs (2 MiB)
__device__ float  g_acc[16];                // [0..7]=mean p4 per batch, [8..15]=mean p16
__device__ int    g_flags[512];             // c4-tile completion flags

__device__ __forceinline__ float clipf(float v, float lo, float hi) {
    return fminf(fmaxf(v, lo), hi);
}
__device__ __forceinline__ uint32_t smem_u32(const void* p) {
    return (uint32_t)__cvta_generic_to_shared(p);
}

// ---------------- prep: clip + fp16 copy + m4/m16 means + weight conversion ----------------
// blocks [0,2048): token prep ; blocks [2048,5120): W1/W4/W16 -> fp16 (+ g_acc/g_flags zero)
__global__ void prep_kernel(const float* __restrict__ vt, const float* __restrict__ W1,
                            const float* __restrict__ W4, const float* __restrict__ W16) {
    int t = threadIdx.x;         // 0..255
    if (blockIdx.x >= 2048) {
        int id = (blockIdx.x - 2048) * 256 + t;   // 0..786431, one float4 each
        if (id < 16) g_acc[id] = 0.f;
        if (id < 512) g_flags[id] = 0;
        int s = id >> 18;
        int j = (id & 262143) << 2;
        const float* src = (s == 0) ? W1 : (s == 1) ? W4 : W16;
        __half* dst = (s == 0) ? g_W1h : (s == 1) ? g_W4h : g_W16h;
        float4 v = *(const float4*)(src + j);
        __half2* hp = (__half2*)(dst + j);
        hp[0] = __floats2half2_rn(v.x, v.y);
        hp[1] = __floats2half2_rn(v.z, v.w);
        return;
    }
    int g = blockIdx.x;          // 0..2047 (16 tokens each)
    int d = t * 4;
    size_t base = (size_t)g * 16 * ND;
    float sx4 = 0.f, sy4 = 0.f, sz4 = 0.f, sw4 = 0.f;
    float sx16 = 0.f, sy16 = 0.f, sz16 = 0.f, sw16 = 0.f;
    #pragma unroll
    for (int r = 0; r < 16; r++) {
        float4 v = *(const float4*)(vt + base + (size_t)r * ND + d);
        v.x = clipf(v.x, -4.f, 4.f);
        v.y = clipf(v.y, -4.f, 4.f);
        v.z = clipf(v.z, -4.f, 4.f);
        v.w = clipf(v.w, -4.f, 4.f);
        __half2* hp = (__half2*)(g_xh + base + (size_t)r * ND + d);
        hp[0] = __floats2half2_rn(v.x, v.y);
        hp[1] = __floats2half2_rn(v.z, v.w);
        sx4 += v.x; sy4 += v.y; sz4 += v.z; sw4 += v.w;
        if ((r & 3) == 3) {
            int r4 = g * 4 + (r >> 2);
            __half2* mp = (__half2*)(g_m4h + (size_t)r4 * ND + d);
            mp[0] = __floats2half2_rn(sx4 * 0.25f, sy4 * 0.25f);
            mp[1] = __floats2half2_rn(sz4 * 0.25f, sw4 * 0.25f);
            sx16 += sx4; sy16 += sy4; sz16 += sz4; sw16 += sw4;
            sx4 = sy4 = sz4 = sw4 = 0.f;
        }
    }
    const float i16 = 1.f / 16.f;
    __half2* mp = (__half2*)(g_m16h + (size_t)g * ND + d);
    mp[0] = __floats2half2_rn(sx16 * i16, sy16 * i16);
    mp[1] = __floats2half2_rn(sz16 * i16, sw16 * i16);
}

// ---------------- GEMM1: fp16, f16 acc, CTA 128x128, BK=64, 2-stage, 3 CTA/SM ----------
// per-nb logit slabs: g_logitsP[nb][row][2] = partial relu(x@W1^T+b1)@W2^T (plain stores)
__global__ void __launch_bounds__(256, 3) gemm1_h(
    const float* __restrict__ pb, const float* __restrict__ pw2)
{
    constexpr int BM  = 128;
    constexpr int STG = (BM + 128) * 128;    // 32768 B per stage (128B rows)
    constexpr int NK  = 16;                  // 1024 / 64

    extern __shared__ __align__(128) char smem[];
    uint32_t sb = smem_u32(smem);
    float* s_b   = (float*)(smem + 2 * STG);
    float* s_w2a = (float*)(smem + 2 * STG + 512);
    float* s_w2b = (float*)(smem + 2 * STG + 1024);

    int tid = threadIdx.x, warp = tid >> 5, lane = tid & 31;
    int wm = warp >> 1, wn = warp & 1;       // 4 x 2 warps, warp tile 32x64
    int mb = blockIdx.y, nb = blockIdx.x;    // mb 0..255, nb 0..7

    if (tid < 128) {
        s_b[tid]   = pb[nb * 128 + tid];
        s_w2a[tid] = pw2[nb * 128 + tid];
        s_w2b[tid] = pw2[ND + nb * 128 + tid];
    }

    const char* Ab = (const char*)g_xh  + (size_t)mb * BM * 2048;
    const char* Bb = (const char*)g_W1h + (size_t)nb * 128 * 2048;

    auto load_stage = [&](int st, int k) {
        uint32_t base = sb + st * STG;
        #pragma unroll
        for (int i = 0; i < 8; i++) {        // 256 rows * 8 chunks = 2048 / 256 thr
            int id = tid + i * 256;
            int row = id >> 3, c = id & 7;
            const char* src = (row < BM)
                ? Ab + (size_t)row * 2048 + (size_t)k * 128 + c * 16
                : Bb + (size_t)(row - BM) * 2048 + (size_t)k * 128 + c * 16;
            uint32_t dst = base + row * 128 + ((c ^ (row & 7)) << 4);
            asm volatile("cp.async.cg.shared.global [%0], [%1], 16;" :: "r"(dst), "l"(src));
        }
        asm volatile("cp.async.commit_group;" ::: "memory");
    };

    uint32_t acch[2][8][2];
    #pragma unroll
    for (int mi = 0; mi < 2; mi++)
        #pragma unroll
        for (int j = 0; j < 8; j++) { acch[mi][j][0] = 0u; acch[mi][j][1] = 0u; }

    // precomputed per-thread ldmatrix row offsets
    int rA[2], sA7[2];
    #pragma unroll
    for (int mi = 0; mi < 2; mi++) {
        int row = wm * 32 + mi * 16 + (lane & 7) + ((lane >> 3) & 1) * 8;
        rA[mi] = row * 128; sA7[mi] = row & 7;
    }
    int rB[4], sB7[4];
    #pragma unroll
    for (int jp = 0; jp < 4; jp++) {
        int row = wn * 64 + (jp * 2 + (lane >> 4)) * 8 + (lane & 7);
        rB[jp] = row * 128; sB7[jp] = row & 7;
    }
    int kA = (lane >> 4);          // A kc low bit
    int kB = ((lane >> 3) & 1);    // B kc low bit

    load_stage(0, 0);

    uint32_t afr[2][2][4], bfr[2][4];

    for (int k = 0; k < NK; k++) {
        asm volatile("cp.async.wait_group 0;" ::: "memory");
        __syncthreads();
        if (k + 1 < NK) load_stage((k + 1) & 1, k + 1);

        uint32_t pA = sb + (k & 1) * STG;
        uint32_t pB = pA + BM * 128;

        auto lda = [&](int ks, uint32_t fr[2][4]) {
            #pragma unroll
            for (int mi = 0; mi < 2; mi++) {
                uint32_t addr = pA + rA[mi] + (((ks * 2 + kA) ^ sA7[mi]) << 4);
                asm volatile("ldmatrix.sync.aligned.m8n8.x4.shared.b16 {%0,%1,%2,%3},[%4];"
                    : "=r"(fr[mi][0]), "=r"(fr[mi][1]), "=r"(fr[mi][2]), "=r"(fr[mi][3])
                    : "r"(addr));
            }
        };
        auto ldb = [&](int ks, int jp, uint32_t fr[4]) {
            uint32_t addr = pB + rB[jp] + (((ks * 2 + kB) ^ sB7[jp]) << 4);
            asm volatile("ldmatrix.sync.aligned.m8n8.x4.shared.b16 {%0,%1,%2,%3},[%4];"
                : "=r"(fr[0]), "=r"(fr[1]), "=r"(fr[2]), "=r"(fr[3])
                : "r"(addr));
        };

        lda(0, afr[0]);
        ldb(0, 0, bfr[0]);
        #pragma unroll
        for (int ks = 0; ks < 4; ks++) {
            if (ks < 3) lda(ks + 1, afr[(ks + 1) & 1]);
            #pragma unroll
            for (int jp = 0; jp < 4; jp++) {
                if (jp < 3)      ldb(ks, jp + 1, bfr[(jp + 1) & 1]);
                else if (ks < 3) ldb(ks + 1, 0, bfr[0]);
                uint32_t* bf = bfr[jp & 1];
                #pragma unroll
                for (int mi = 0; mi < 2; mi++) {
                    uint32_t* af = afr[ks & 1][mi];
                    asm volatile(
                        "mma.sync.aligned.m16n8k16.row.col.f16.f16.f16.f16 "
                        "{%0,%1},{%2,%3,%4,%5},{%6,%7},{%0,%1};"
                        : "+r"(acch[mi][jp * 2][0]), "+r"(acch[mi][jp * 2][1])
                        : "r"(af[0]), "r"(af[1]), "r"(af[2]), "r"(af[3]),
                          "r"(bf[0]), "r"(bf[1]));
                    asm volatile(
                        "mma.sync.aligned.m16n8k16.row.col.f16.f16.f16.f16 "
                        "{%0,%1},{%2,%3,%4,%5},{%6,%7},{%0,%1};"
                        : "+r"(acch[mi][jp * 2 + 1][0]), "+r"(acch[mi][jp * 2 + 1][1])
                        : "r"(af[0]), "r"(af[1]), "r"(af[2]), "r"(af[3]),
                          "r"(bf[2]), "r"(bf[3]));
                }
            }
        }
    }

    // epilogue: h = relu(acc + b1); partial dot with W2; plain stores to per-nb slab
    #pragma unroll
    for (int mi = 0; mi < 2; mi++) {
        float s[2][2] = {{0.f, 0.f}, {0.f, 0.f}};
        #pragma unroll
        for (int j = 0; j < 8; j++) {
            int colb = wn * 64 + j * 8 + (lane & 3) * 2;
            float2 v0 = __half22float2(*(__half2*)&acch[mi][j][0]);
            float2 v1 = __half22float2(*(__half2*)&acch[mi][j][1]);
            float h00 = fmaxf(v0.x + s_b[colb],     0.f);
            float h01 = fmaxf(v0.y + s_b[colb + 1], 0.f);
            float h10 = fmaxf(v1.x + s_b[colb],     0.f);
            float h11 = fmaxf(v1.y + s_b[colb + 1], 0.f);
            s[0][0] += h00 * s_w2a[colb] + h01 * s_w2a[colb + 1];
            s[0][1] += h00 * s_w2b[colb] + h01 * s_w2b[colb + 1];
            s[1][0] += h10 * s_w2a[colb] + h11 * s_w2a[colb + 1];
            s[1][1] += h10 * s_w2b[colb] + h11 * s_w2b[colb + 1];
        }
        #pragma unroll
        for (int off = 1; off < 4; off <<= 1)
            #pragma unroll
            for (int hh = 0; hh < 2; hh++) {
                s[hh][0] += __shfl_xor_sync(0xffffffffu, s[hh][0], off);
                s[hh][1] += __shfl_xor_sync(0xffffffffu, s[hh][1], off);
            }
        // combine the two wn column-halves through smem, wn==1 stores to gmem
        __syncthreads();
        float* s_red = (float*)(smem + 2 * STG + 1536);  // 128 rows * 2 floats
        if (wn == 0 && (lane & 3) == 0) {
            #pragma unroll
            for (int hh = 0; hh < 2; hh++) {
                int rloc = wm * 32 + mi * 16 + hh * 8 + (lane >> 2);
                s_red[2 * rloc]     = s[hh][0];
                s_red[2 * rloc + 1] = s[hh][1];
            }
        }
        __syncthreads();
        if (wn == 1 && (lane & 3) == 0) {
            #pragma unroll
            for (int hh = 0; hh < 2; hh++) {
                int rloc = wm * 32 + mi * 16 + hh * 8 + (lane >> 2);
                int row = mb * BM + rloc;
                float2 o = {s[hh][0] + s_red[2 * rloc], s[hh][1] + s_red[2 * rloc + 1]};
                *(float2*)&g_logitsP[((size_t)nb * NM1 + row) * 2] = o;
            }
        }
    }
}

// ---------------- flat c4/c16 GEMM: 640 equal tiles, flag handoff for c16 RMW ------------
// blockIdx 0..511:  c4 tile  (mb=id>>2 in 0..127, nb=id&3) -> write out rows mb*64..
// blockIdx 512..639: c16 tile (mb=id>>2 in 0..31, nb=id&3) -> RMW out rows bb*1024+(mb&3)*64..
__global__ void __launch_bounds__(256, 2) cgemm_h(
    const float* __restrict__ pb4, const float* __restrict__ pb16, float* __restrict__ outp)
{
    constexpr int BM  = 64;
    constexpr int STG = (BM + 256) * 64;     // 20480
    constexpr int NK  = 32;

    extern __shared__ __align__(128) char smem[];
    uint32_t sb = smem_u32(smem);
    float* s_b = (float*)(smem + 3 * STG);

    int tid = threadIdx.x, warp = tid >> 5, lane = tid & 31;
    int wm = warp >> 2, wn = warp & 3;       // 2 x 4; warp tile 32x64
    int tno = blockIdx.x;
    bool is16 = (tno >= 512);
    int id = is16 ? (tno - 512) : tno;
    int mb = id >> 2, nb = id & 3;

    const char* Ab = is16 ? (const char*)(g_m16h + (size_t)mb * 64 * ND)
                          : (const char*)(g_m4h  + (size_t)mb * 64 * ND);
    const char* Bb = (is16 ? (const char*)g_W16h : (const char*)g_W4h) + (size_t)nb * 256 * 2048;
    const float* bias = is16 ? pb16 : pb4;
    int bb = is16 ? (mb >> 2) : (mb >> 4);
    size_t outrow0 = is16 ? ((size_t)bb * 1024 + (mb & 3) * 64) : ((size_t)mb * 64);
    int flagIdx = is16 ? ((int)(outrow0 >> 6) * 4 + nb) : tno;

    float a0 = g_acc[bb], a1 = g_acc[8 + bb];
    float amix = (is16 ? a1 : a0) / (a0 + a1 + 1e-7f);

    if (tid < 256) s_b[tid] = bias[nb * 256 + tid];

    auto load_stage = [&](int st, int k) {
        uint32_t base = sb + st * STG;
        #pragma unroll
        for (int i = 0; i < 5; i++) {        // (64+256)*4 = 1280 chunks
            int id2 = tid + i * 256;
            bool isB = id2 >= BM * 4;
            int l2 = isB ? id2 - BM * 4 : id2;
            int row = l2 >> 2, c = l2 & 3;
            const char* src = (isB ? Bb : Ab) + (size_t)row * 2048 + (size_t)k * 64 + c * 16;
            uint32_t dst = base + (isB ? BM * 64 : 0) + row * 64 + ((c ^ ((row >> 1) & 3)) << 4);
            asm volatile("cp.async.cg.shared.global [%0], [%1], 16;" :: "r"(dst), "l"(src));
        }
        asm volatile("cp.async.commit_group;" ::: "memory");
    };

    float accf[2][8][4];
    #pragma unroll
    for (int mi = 0; mi < 2; mi++)
        #pragma unroll
        for (int j = 0; j < 8; j++)
            #pragma unroll
            for (int q = 0; q < 4; q++) accf[mi][j][q] = 0.f;

    load_stage(0, 0);
    load_stage(1, 1);

    int st = 0;
    for (int k = 0; k < NK; k++) {
        asm volatile("cp.async.wait_group 1;" ::: "memory");
        __syncthreads();
        if (k + 2 < NK) {
            int st2 = st + 2; if (st2 >= 3) st2 -= 3;
            load_stage(st2, k + 2);
        } else {
            asm volatile("cp.async.commit_group;" ::: "memory");
        }

        uint32_t pA = sb + st * STG;
        uint32_t pB = pA + BM * 64;
        #pragma unroll
        for (int ks = 0; ks < 2; ks++) {
            uint32_t afr[2][4], bfr[8][2];
            #pragma unroll
            for (int mi = 0; mi < 2; mi++) {
                int row = wm * 32 + mi * 16 + (lane & 7) + ((lane >> 3) & 1) * 8;
                int kc = ks * 2 + (lane >> 4);
                uint32_t addr = pA + row * 64 + ((kc ^ ((row >> 1) & 3)) << 4);
                asm volatile("ldmatrix.sync.aligned.m8n8.x4.shared.b16 {%0,%1,%2,%3},[%4];"
                    : "=r"(afr[mi][0]), "=r"(afr[mi][1]), "=r"(afr[mi][2]), "=r"(afr[mi][3])
                    : "r"(addr));
            }
            #pragma unroll
            for (int j = 0; j < 8; j += 2) {
                int row = wn * 64 + (j + (lane >> 4)) * 8 + (lane & 7);
                int kc = ks * 2 + ((lane >> 3) & 1);
                uint32_t addr = pB + row * 64 + ((kc ^ ((row >> 1) & 3)) << 4);
                asm volatile("ldmatrix.sync.aligned.m8n8.x4.shared.b16 {%0,%1,%2,%3},[%4];"
                    : "=r"(bfr[j][0]), "=r"(bfr[j][1]), "=r"(bfr[j + 1][0]), "=r"(bfr[j + 1][1])
                    : "r"(addr));
            }
            #pragma unroll
            for (int mi = 0; mi < 2; mi++)
                #pragma unroll
                for (int j = 0; j < 8; j++) {
                    asm volatile(
                        "mma.sync.aligned.m16n8k16.row.col.f32.f16.f16.f32 "
                        "{%0,%1,%2,%3},{%4,%5,%6,%7},{%8,%9},{%0,%1,%2,%3};"
                        : "+f"(accf[mi][j][0]), "+f"(accf[mi][j][1]),
                          "+f"(accf[mi][j][2]), "+f"(accf[mi][j][3])
                        : "r"(afr[mi][0]), "r"(afr[mi][1]), "r"(afr[mi][2]), "r"(afr[mi][3]),
                          "r"(bfr[j][0]), "r"(bfr[j][1]));
                }
        }
        st++; if (st >= 3) st -= 3;
    }

    if (is16) {
        // acquire: wait for the producing c4 tile, then fence before reading out
        if (tid == 0) {
            while (atomicAdd(&g_flags[flagIdx], 0) == 0) { }
            __threadfence();
        }
        __syncthreads();
    }

    // epilogue: c4 write (+release flag), c16 RMW with final clip
    #pragma unroll
    for (int mi = 0; mi < 2; mi++) {
        #pragma unroll
        for (int hh = 0; hh < 2; hh++) {
            int rloc = wm * 32 + mi * 16 + hh * 8 + (lane >> 2);
            float* obase = outp + (outrow0 + rloc) * ND + nb * 256 + wn * 64;
            #pragma unroll
            for (int j = 0; j < 8; j++) {
                int cl = wn * 64 + j * 8 + (lane & 3) * 2;
                float v0 = amix * clipf(accf[mi][j][hh * 2 + 0] + s_b[cl],     -6.f, 6.f);
                float v1 = amix * clipf(accf[mi][j][hh * 2 + 1] + s_b[cl + 1], -6.f, 6.f);
                float* op = obase + j * 8 + (lane & 3) * 2;
                if (!is16) {
                    float2 o = {v0, v1};
                    *(float2*)op = o;
                } else {
                    float2 o = *(float2*)op;
                    o.x = clipf(o.x + v0, -6.f, 6.f);
                    o.y = clipf(o.y + v1, -6.f, 6.f);
                    *(float2*)op = o;
                }
            }
        }
    }

    if (!is16) {
        // release: all stores visible, then set flag
        __threadfence();
        __syncthreads();
        if (tid == 0) atomicExch(&g_flags[flagIdx], 1);
    }
}

// ---------------- router partial: sum slabs, gumbel-softmax, atomic per-batch means ----------
__global__ void router_kernel(const float* __restrict__ gumbel, const float* __restrict__ b2) {
    int b = blockIdx.y;          // batch
    int sp = blockIdx.x;         // split 0..7
    int t = threadIdx.x;
    float b20 = __ldg(b2), b21 = __ldg(b2 + 1);
    float s0 = 0.f, s1 = 0.f;
    #pragma unroll 2
    for (int q = 0; q < 2; q++) {
        int tk = sp * 512 + q * 256 + t;
        int idx = b * NL + tk;
        float a0 = 0.f, a1 = 0.f;
        #pragma unroll
        for (int nb = 0; nb < 8; nb++) {
            float2 v = *(const float2*)&g_logitsP[((size_t)nb * NM1 + idx) * 2];
            a0 += v.x; a1 += v.y;
        }
        float l0 = clipf(a0 + b20, -15.f, 15.f);
        float l1 = clipf(a1 + b21, -15.f, 15.f);
        float u0 = (l0 + gumbel[2 * idx])     * 2.0f;   // /TEMP, TEMP=0.5
        float u1 = (l1 + gumbel[2 * idx + 1]) * 2.0f;
        float p0 = 1.f / (1.f + expf(u1 - u0));
        float p1 = 1.f / (1.f + expf(u0 - u1));
        s0 += clipf(p0, 1e-7f, 1.f - 1e-7f);
        s1 += clipf(p1, 1e-7f, 1.f - 1e-7f);
    }
    // warp reduce then block reduce
    #pragma unroll
    for (int off = 16; off > 0; off >>= 1) {
        s0 += __shfl_xor_sync(0xffffffffu, s0, off);
        s1 += __shfl_xor_sync(0xffffffffu, s1, off);
    }
    __shared__ float r0[8], r1[8];
    int warp = t >> 5, lane = t & 31;
    if (lane == 0) { r0[warp] = s0; r1[warp] = s1; }
    __syncthreads();
    if (warp == 0) {
        float v0 = (lane < 8) ? r0[lane] : 0.f;
        float v1 = (lane < 8) ? r1[lane] : 0.f;
        #pragma unroll
        for (int off = 4; off > 0; off >>= 1) {
            v0 += __shfl_xor_sync(0xffffffffu, v0, off);
            v1 += __shfl_xor_sync(0xffffffffu, v1, off);
        }
        if (lane == 0) {
            atomicAdd(&g_acc[b],     v0 / (float)NL);
            atomicAdd(&g_acc[8 + b], v1 / (float)NL);
        }
    }
}

// ---------------- launch ----------------
extern "C" void kernel_launch(void* const* d_in, const int* in_sizes, int n_in,
                              void* d_out, int out_size) {
    const float* vt     = (const float*)d_in[0];
    const float* gumbel = (const float*)d_in[1];
    const float* W1     = (const float*)d_in[2];
    const float* b1     = (const float*)d_in[3];
    const float* W2     = (const float*)d_in[4];
    const float* b2     = (const float*)d_in[5];
    const float* W4     = (const float*)d_in[6];
    const float* b4     = (const float*)d_in[7];
    const float* W16    = (const float*)d_in[8];
    const float* b16    = (const float*)d_in[9];
    float* out = (float*)d_out;

    const int SM1  = 2 * (128 + 128) * 128 + 2560;  // 68096 (gemm1: 2 stages + params + red)
    const int SM64 = 3 * (64 + 256) * 64 + 3072;    // 64512 (cgemm, 3-stage)
    cudaFuncSetAttribute(gemm1_h, cudaFuncAttributeMaxDynamicSharedMemorySize, SM1);
    cudaFuncSetAttribute(cgemm_h, cudaFuncAttributeMaxDynamicSharedMemorySize, SM64);

    prep_kernel<<<5120, 256>>>(vt, W1, W4, W16);
    gemm1_h<<<dim3(8, 256), 256, SM1>>>(b1, W2);
    router_kernel<<<dim3(8, 8), 256>>>(gumbel, b2);
    cgemm_h<<<640, 256, SM64>>>(b4, b16, out);
}

// round 16
// speedup vs baseline: 1.0268x; 1.0268x over previous
#include <cuda_runtime.h>
#include <cuda_fp16.h>
#include <cstdint>

#define NB 8
#define NL 4096
#define ND 1024
#define NM1 (NB*NL)      // 32768
#define NM4 (NM1/4)      // 8192
#define NM16 (NM1/16)    // 2048

// ---------------- static device scratch ----------------
__device__ __half g_xh[(size_t)NM1*ND];     // clipped x, fp16 (64 MiB)
__device__ __half g_m4h[(size_t)NM4*ND];    // group-4 means, fp16
__device__ __half g_m16h[(size_t)NM16*ND];  // group-16 means, fp16
__device__ __half g_W1h[(size_t)ND*ND];
__device__ __half g_W4h[(size_t)ND*ND];
__device__ __half g_W16h[(size_t)ND*ND];
__device__ float  g_logitsP[(size_t)8*NM1*2];  // per-nb logit slabs (2 MiB)
__device__ float  g_acc[16];                // [0..7]=mean p4 per batch, [8..15]=mean p16

__device__ __forceinline__ float clipf(float v, float lo, float hi) {
    return fminf(fmaxf(v, lo), hi);
}
__device__ __forceinline__ uint32_t smem_u32(const void* p) {
    return (uint32_t)__cvta_generic_to_shared(p);
}

// ---------------- prep: clip + fp16 copy + m4/m16 means + weight conversion ----------------
// blocks [0,2048): token prep ; blocks [2048,5120): W1/W4/W16 -> fp16 (+ g_acc zero)
__global__ void prep_kernel(const float* __restrict__ vt, const float* __restrict__ W1,
                            const float* __restrict__ W4, const float* __restrict__ W16) {
    int t = threadIdx.x;         // 0..255
    if (blockIdx.x >= 2048) {
        int id = (blockIdx.x - 2048) * 256 + t;   // 0..786431, one float4 each
        if (id < 16) g_acc[id] = 0.f;
        int s = id >> 18;
        int j = (id & 262143) << 2;
        const float* src = (s == 0) ? W1 : (s == 1) ? W4 : W16;
        __half* dst = (s == 0) ? g_W1h : (s == 1) ? g_W4h : g_W16h;
        float4 v = *(const float4*)(src + j);
        __half2* hp = (__half2*)(dst + j);
        hp[0] = __floats2half2_rn(v.x, v.y);
        hp[1] = __floats2half2_rn(v.z, v.w);
        return;
    }
    int g = blockIdx.x;          // 0..2047 (16 tokens each)
    int d = t * 4;
    size_t base = (size_t)g * 16 * ND;
    float sx4 = 0.f, sy4 = 0.f, sz4 = 0.f, sw4 = 0.f;
    float sx16 = 0.f, sy16 = 0.f, sz16 = 0.f, sw16 = 0.f;
    #pragma unroll
    for (int r = 0; r < 16; r++) {
        float4 v = *(const float4*)(vt + base + (size_t)r * ND + d);
        v.x = clipf(v.x, -4.f, 4.f);
        v.y = clipf(v.y, -4.f, 4.f);
        v.z = clipf(v.z, -4.f, 4.f);
        v.w = clipf(v.w, -4.f, 4.f);
        __half2* hp = (__half2*)(g_xh + base + (size_t)r * ND + d);
        hp[0] = __floats2half2_rn(v.x, v.y);
        hp[1] = __floats2half2_rn(v.z, v.w);
        sx4 += v.x; sy4 += v.y; sz4 += v.z; sw4 += v.w;
        if ((r & 3) == 3) {
            int r4 = g * 4 + (r >> 2);
            __half2* mp = (__half2*)(g_m4h + (size_t)r4 * ND + d);
            mp[0] = __floats2half2_rn(sx4 * 0.25f, sy4 * 0.25f);
            mp[1] = __floats2half2_rn(sz4 * 0.25f, sw4 * 0.25f);
            sx16 += sx4; sy16 += sy4; sz16 += sz4; sw16 += sw4;
            sx4 = sy4 = sz4 = sw4 = 0.f;
        }
    }
    const float i16 = 1.f / 16.f;
    __half2* mp = (__half2*)(g_m16h + (size_t)g * ND + d);
    mp[0] = __floats2half2_rn(sx16 * i16, sy16 * i16);
    mp[1] = __floats2half2_rn(sz16 * i16, sw16 * i16);
}

// ---------------- GEMM1: fp16, f16 acc, CTA 128x128, BK=64, 2-stage, 3 CTA/SM ----------
// per-nb logit slabs: g_logitsP[nb][row][2] = partial relu(x@W1^T+b1)@W2^T (plain stores)
__global__ void __launch_bounds__(256, 3) gemm1_h(
    const float* __restrict__ pb, const float* __restrict__ pw2)
{
    constexpr int BM  = 128;
    constexpr int STG = (BM + 128) * 128;    // 32768 B per stage (128B rows)
    constexpr int NK  = 16;                  // 1024 / 64

    extern __shared__ __align__(128) char smem[];
    uint32_t sb = smem_u32(smem);
    float* s_b   = (float*)(smem + 2 * STG);
    float* s_w2a = (float*)(smem + 2 * STG + 512);
    float* s_w2b = (float*)(smem + 2 * STG + 1024);

    int tid = threadIdx.x, warp = tid >> 5, lane = tid & 31;
    int wm = warp >> 1, wn = warp & 1;       // 4 x 2 warps, warp tile 32x64
    int mb = blockIdx.y, nb = blockIdx.x;    // mb 0..255, nb 0..7

    if (tid < 128) {
        s_b[tid]   = pb[nb * 128 + tid];
        s_w2a[tid] = pw2[nb * 128 + tid];
        s_w2b[tid] = pw2[ND + nb * 128 + tid];
    }

    const char* Ab = (const char*)g_xh  + (size_t)mb * BM * 2048;
    const char* Bb = (const char*)g_W1h + (size_t)nb * 128 * 2048;

    auto load_stage = [&](int st, int k) {
        uint32_t base = sb + st * STG;
        #pragma unroll
        for (int i = 0; i < 8; i++) {        // 256 rows * 8 chunks = 2048 / 256 thr
            int id = tid + i * 256;
            int row = id >> 3, c = id & 7;
            const char* src = (row < BM)
                ? Ab + (size_t)row * 2048 + (size_t)k * 128 + c * 16
                : Bb + (size_t)(row - BM) * 2048 + (size_t)k * 128 + c * 16;
            uint32_t dst = base + row * 128 + ((c ^ (row & 7)) << 4);
            asm volatile("cp.async.cg.shared.global [%0], [%1], 16;" :: "r"(dst), "l"(src));
        }
        asm volatile("cp.async.commit_group;" ::: "memory");
    };

    uint32_t acch[2][8][2];
    #pragma unroll
    for (int mi = 0; mi < 2; mi++)
        #pragma unroll
        for (int j = 0; j < 8; j++) { acch[mi][j][0] = 0u; acch[mi][j][1] = 0u; }

    // precomputed per-thread ldmatrix row offsets
    int rA[2], sA7[2];
    #pragma unroll
    for (int mi = 0; mi < 2; mi++) {
        int row = wm * 32 + mi * 16 + (lane & 7) + ((lane >> 3) & 1) * 8;
        rA[mi] = row * 128; sA7[mi] = row & 7;
    }
    int rB[4], sB7[4];
    #pragma unroll
    for (int jp = 0; jp < 4; jp++) {
        int row = wn * 64 + (jp * 2 + (lane >> 4)) * 8 + (lane & 7);
        rB[jp] = row * 128; sB7[jp] = row & 7;
    }
    int kA = (lane >> 4);          // A kc low bit
    int kB = ((lane >> 3) & 1);    // B kc low bit

    load_stage(0, 0);

    uint32_t afr[2][2][4], bfr[2][4];

    for (int k = 0; k < NK; k++) {
        asm volatile("cp.async.wait_group 0;" ::: "memory");
        __syncthreads();
        if (k + 1 < NK) load_stage((k + 1) & 1, k + 1);

        uint32_t pA = sb + (k & 1) * STG;
        uint32_t pB = pA + BM * 128;

        auto lda = [&](int ks, uint32_t fr[2][4]) {
            #pragma unroll
            for (int mi = 0; mi < 2; mi++) {
                uint32_t addr = pA + rA[mi] + (((ks * 2 + kA) ^ sA7[mi]) << 4);
                asm volatile("ldmatrix.sync.aligned.m8n8.x4.shared.b16 {%0,%1,%2,%3},[%4];"
                    : "=r"(fr[mi][0]), "=r"(fr[mi][1]), "=r"(fr[mi][2]), "=r"(fr[mi][3])
                    : "r"(addr));
            }
        };
        auto ldb = [&](int ks, int jp, uint32_t fr[4]) {
            uint32_t addr = pB + rB[jp] + (((ks * 2 + kB) ^ sB7[jp]) << 4);
            asm volatile("ldmatrix.sync.aligned.m8n8.x4.shared.b16 {%0,%1,%2,%3},[%4];"
                : "=r"(fr[0]), "=r"(fr[1]), "=r"(fr[2]), "=r"(fr[3])
                : "r"(addr));
        };

        lda(0, afr[0]);
        ldb(0, 0, bfr[0]);
        #pragma unroll
        for (int ks = 0; ks < 4; ks++) {
            if (ks < 3) lda(ks + 1, afr[(ks + 1) & 1]);
            #pragma unroll
            for (int jp = 0; jp < 4; jp++) {
                if (jp < 3)      ldb(ks, jp + 1, bfr[(jp + 1) & 1]);
                else if (ks < 3) ldb(ks + 1, 0, bfr[0]);
                uint32_t* bf = bfr[jp & 1];
                #pragma unroll
                for (int mi = 0; mi < 2; mi++) {
                    uint32_t* af = afr[ks & 1][mi];
                    asm volatile(
                        "mma.sync.aligned.m16n8k16.row.col.f16.f16.f16.f16 "
                        "{%0,%1},{%2,%3,%4,%5},{%6,%7},{%0,%1};"
                        : "+r"(acch[mi][jp * 2][0]), "+r"(acch[mi][jp * 2][1])
                        : "r"(af[0]), "r"(af[1]), "r"(af[2]), "r"(af[3]),
                          "r"(bf[0]), "r"(bf[1]));
                    asm volatile(
                        "mma.sync.aligned.m16n8k16.row.col.f16.f16.f16.f16 "
                        "{%0,%1},{%2,%3,%4,%5},{%6,%7},{%0,%1};"
                        : "+r"(acch[mi][jp * 2 + 1][0]), "+r"(acch[mi][jp * 2 + 1][1])
                        : "r"(af[0]), "r"(af[1]), "r"(af[2]), "r"(af[3]),
                          "r"(bf[2]), "r"(bf[3]));
                }
            }
        }
    }

    // epilogue: h = relu(acc + b1); partial dot with W2; plain stores to per-nb slab
    #pragma unroll
    for (int mi = 0; mi < 2; mi++) {
        float s[2][2] = {{0.f, 0.f}, {0.f, 0.f}};
        #pragma unroll
        for (int j = 0; j < 8; j++) {
            int colb = wn * 64 + j * 8 + (lane & 3) * 2;
            float2 v0 = __half22float2(*(__half2*)&acch[mi][j][0]);
            float2 v1 = __half22float2(*(__half2*)&acch[mi][j][1]);
            float h00 = fmaxf(v0.x + s_b[colb],     0.f);
            float h01 = fmaxf(v0.y + s_b[colb + 1], 0.f);
            float h10 = fmaxf(v1.x + s_b[colb],     0.f);
            float h11 = fmaxf(v1.y + s_b[colb + 1], 0.f);
            s[0][0] += h00 * s_w2a[colb] + h01 * s_w2a[colb + 1];
            s[0][1] += h00 * s_w2b[colb] + h01 * s_w2b[colb + 1];
            s[1][0] += h10 * s_w2a[colb] + h11 * s_w2a[colb + 1];
            s[1][1] += h10 * s_w2b[colb] + h11 * s_w2b[colb + 1];
        }
        #pragma unroll
        for (int off = 1; off < 4; off <<= 1)
            #pragma unroll
            for (int hh = 0; hh < 2; hh++) {
                s[hh][0] += __shfl_xor_sync(0xffffffffu, s[hh][0], off);
                s[hh][1] += __shfl_xor_sync(0xffffffffu, s[hh][1], off);
            }
        // combine the two wn column-halves through smem, wn==1 stores to gmem
        __syncthreads();
        float* s_red = (float*)(smem + 2 * STG + 1536);  // 128 rows * 2 floats
        if (wn == 0 && (lane & 3) == 0) {
            #pragma unroll
            for (int hh = 0; hh < 2; hh++) {
                int rloc = wm * 32 + mi * 16 + hh * 8 + (lane >> 2);
                s_red[2 * rloc]     = s[hh][0];
                s_red[2 * rloc + 1] = s[hh][1];
            }
        }
        __syncthreads();
        if (wn == 1 && (lane & 3) == 0) {
            #pragma unroll
            for (int hh = 0; hh < 2; hh++) {
                int rloc = wm * 32 + mi * 16 + hh * 8 + (lane >> 2);
                int row = mb * BM + rloc;
                float2 o = {s[hh][0] + s_red[2 * rloc], s[hh][1] + s_red[2 * rloc + 1]};
                *(float2*)&g_logitsP[((size_t)nb * NM1 + row) * 2] = o;
            }
        }
    }
}

// ---------------- combined c4/c16 GEMM, CTA 64x256, BK=64, 2-stage, frag-pipelined ----------
// Tiles mb 0..31 ("fused"): out rows bb*1024+[0,256) — phase 0 = c4 write, phase 1 = c16 RMW.
// Tiles mb 32..127: c4-only, out rows bb*1024+[256,1024).
__global__ void __launch_bounds__(256, 2) cgemm_h(
    const float* __restrict__ pb4, const float* __restrict__ pb16, float* __restrict__ outp)
{
    constexpr int BM  = 64;
    constexpr int STG = (BM + 256) * 128;    // 40960 B per stage (128B rows)
    constexpr int NK  = 16;                  // 1024 / 64

    extern __shared__ __align__(128) char smem[];
    uint32_t sb = smem_u32(smem);
    float* s_b = (float*)(smem + 2 * STG);

    int tid = threadIdx.x, warp = tid >> 5, lane = tid & 31;
    int wm = warp >> 2, wn = warp & 3;       // 2 x 4; warp tile 32x64
    int mb = blockIdx.y, nb = blockIdx.x;

    bool fused = (mb < 32);
    int bb, l0;
    if (fused) { bb = mb >> 2;      l0 = (mb & 3) * 64; }
    else       { int c = mb - 32;   bb = c / 12; l0 = ((c % 12) + 4) * 64; }
    size_t outrow0 = (size_t)bb * 1024 + l0;
    int nph = fused ? 2 : 1;

    float a0 = g_acc[bb], a1 = g_acc[8 + bb];
    float inv = 1.f / (a0 + a1 + 1e-7f);

    // per-thread ldmatrix row offsets (phase-invariant)
    int rA[2], sA7[2];
    #pragma unroll
    for (int mi = 0; mi < 2; mi++) {
        int row = wm * 32 + mi * 16 + (lane & 7) + ((lane >> 3) & 1) * 8;
        rA[mi] = row * 128; sA7[mi] = row & 7;
    }
    int rB[4], sB7[4];
    #pragma unroll
    for (int jp = 0; jp < 4; jp++) {
        int row = wn * 64 + (jp * 2 + (lane >> 4)) * 8 + (lane & 7);
        rB[jp] = row * 128; sB7[jp] = row & 7;
    }
    int kA = (lane >> 4);
    int kB = ((lane >> 3) & 1);

    for (int p = 0; p < nph; p++) {
        const char* Ab = p
            ? (const char*)(g_m16h + ((size_t)bb * 256 + l0) * ND)
            : (const char*)(g_m4h  + outrow0 * ND);
        const char* Bb = (p ? (const char*)g_W16h : (const char*)g_W4h) + (size_t)nb * 256 * 2048;
        const float* bias = p ? pb16 : pb4;
        float amix = (p ? a1 : a0) * inv;

        __syncthreads();                     // protect s_b reuse across phases
        if (tid < 256) s_b[tid] = bias[nb * 256 + tid];

        auto load_stage = [&](int st, int k) {
            uint32_t base = sb + st * STG;
            #pragma unroll
            for (int i = 0; i < 10; i++) {   // 320 rows * 8 chunks = 2560 / 256 thr
                int id = tid + i * 256;
                int row = id >> 3, c = id & 7;
                const char* src = (row < BM)
                    ? Ab + (size_t)row * 2048 + (size_t)k * 128 + c * 16
                    : Bb + (size_t)(row - BM) * 2048 + (size_t)k * 128 + c * 16;
                uint32_t dst = base + row * 128 + ((c ^ (row & 7)) << 4);
                asm volatile("cp.async.cg.shared.global [%0], [%1], 16;" :: "r"(dst), "l"(src));
            }
            asm volatile("cp.async.commit_group;" ::: "memory");
        };

        float accf[2][8][4];
        #pragma unroll
        for (int mi = 0; mi < 2; mi++)
            #pragma unroll
            for (int j = 0; j < 8; j++)
                #pragma unroll
                for (int q = 0; q < 4; q++) accf[mi][j][q] = 0.f;

        load_stage(0, 0);

        uint32_t afr[2][2][4], bfr[2][4];

        for (int k = 0; k < NK; k++) {
            asm volatile("cp.async.wait_group 0;" ::: "memory");
            __syncthreads();
            if (k + 1 < NK) load_stage((k + 1) & 1, k + 1);

            uint32_t pA = sb + (k & 1) * STG;
            uint32_t pB = pA + BM * 128;

            auto lda = [&](int ks, uint32_t fr[2][4]) {
                #pragma unroll
                for (int mi = 0; mi < 2; mi++) {
                    uint32_t addr = pA + rA[mi] + (((ks * 2 + kA) ^ sA7[mi]) << 4);
                    asm volatile("ldmatrix.sync.aligned.m8n8.x4.shared.b16 {%0,%1,%2,%3},[%4];"
                        : "=r"(fr[mi][0]), "=r"(fr[mi][1]), "=r"(fr[mi][2]), "=r"(fr[mi][3])
                        : "r"(addr));
                }
            };
            auto ldb = [&](int ks, int jp, uint32_t fr[4]) {
                uint32_t addr = pB + rB[jp] + (((ks * 2 + kB) ^ sB7[jp]) << 4);
                asm volatile("ldmatrix.sync.aligned.m8n8.x4.shared.b16 {%0,%1,%2,%3},[%4];"
                    : "=r"(fr[0]), "=r"(fr[1]), "=r"(fr[2]), "=r"(fr[3])
                    : "r"(addr));
            };

            lda(0, afr[0]);
            ldb(0, 0, bfr[0]);
            #pragma unroll
            for (int ks = 0; ks < 4; ks++) {
                if (ks < 3) lda(ks + 1, afr[(ks + 1) & 1]);
                #pragma unroll
                for (int jp = 0; jp < 4; jp++) {
                    if (jp < 3)      ldb(ks, jp + 1, bfr[(jp + 1) & 1]);
                    else if (ks < 3) ldb(ks + 1, 0, bfr[0]);
                    uint32_t* bf = bfr[jp & 1];
                    #pragma unroll
                    for (int mi = 0; mi < 2; mi++) {
                        uint32_t* af = afr[ks & 1][mi];
                        asm volatile(
                            "mma.sync.aligned.m16n8k16.row.col.f32.f16.f16.f32 "
                            "{%0,%1,%2,%3},{%4,%5,%6,%7},{%8,%9},{%0,%1,%2,%3};"
                            : "+f"(accf[mi][jp * 2][0]), "+f"(accf[mi][jp * 2][1]),
                              "+f"(accf[mi][jp * 2][2]), "+f"(accf[mi][jp * 2][3])
                            : "r"(af[0]), "r"(af[1]), "r"(af[2]), "r"(af[3]),
                              "r"(bf[0]), "r"(bf[1]));
                        asm volatile(
                            "mma.sync.aligned.m16n8k16.row.col.f32.f16.f16.f32 "
                            "{%0,%1,%2,%3},{%4,%5,%6,%7},{%8,%9},{%0,%1,%2,%3};"
                            : "+f"(accf[mi][jp * 2 + 1][0]), "+f"(accf[mi][jp * 2 + 1][1]),
                              "+f"(accf[mi][jp * 2 + 1][2]), "+f"(accf[mi][jp * 2 + 1][3])
                            : "r"(af[0]), "r"(af[1]), "r"(af[2]), "r"(af[3]),
                              "r"(bf[2]), "r"(bf[3]));
                    }
                }
            }
        }

        // epilogue: p==0 plain write (c4), p==1 RMW with final clip (c16)
        #pragma unroll
        for (int mi = 0; mi < 2; mi++) {
            #pragma unroll
            for (int hh = 0; hh < 2; hh++) {
                int rloc = wm * 32 + mi * 16 + hh * 8 + (lane >> 2);
                float* obase = outp + (outrow0 + rloc) * ND + nb * 256 + wn * 64;
                #pragma unroll
                for (int j = 0; j < 8; j++) {
                    int cl = wn * 64 + j * 8 + (lane & 3) * 2;
                    float v0 = amix * clipf(accf[mi][j][hh * 2 + 0] + s_b[cl],     -6.f, 6.f);
                    float v1 = amix * clipf(accf[mi][j][hh * 2 + 1] + s_b[cl + 1], -6.f, 6.f);
                    float* op = obase + j * 8 + (lane & 3) * 2;
                    if (p == 0) {
                        float2 o = {v0, v1};
                        *(float2*)op = o;
                    } else {
                        float2 o = *(float2*)op;
                        o.x = clipf(o.x + v0, -6.f, 6.f);
                        o.y = clipf(o.y + v1, -6.f, 6.f);
                        *(float2*)op = o;
                    }
                }
            }
        }
    }
}

// ---------------- router partial: sum slabs, gumbel-softmax, atomic per-batch means ----------
__global__ void router_kernel(const float* __restrict__ gumbel, const float* __restrict__ b2) {
    int b = blockIdx.y;          // batch
    int sp = blockIdx.x;         // split 0..7
    int t = threadIdx.x;
    float b20 = __ldg(b2), b21 = __ldg(b2 + 1);
    float s0 = 0.f, s1 = 0.f;
    #pragma unroll 2
    for (int q = 0; q < 2; q++) {
        int tk = sp * 512 + q * 256 + t;
        int idx = b * NL + tk;
        float a0 = 0.f, a1 = 0.f;
        #pragma unroll
        for (int nb = 0; nb < 8; nb++) {
            float2 v = *(const float2*)&g_logitsP[((size_t)nb * NM1 + idx) * 2];
            a0 += v.x; a1 += v.y;
        }
        float l0 = clipf(a0 + b20, -15.f, 15.f);
        float l1 = clipf(a1 + b21, -15.f, 15.f);
        float u0 = (l0 + gumbel[2 * idx])     * 2.0f;   // /TEMP, TEMP=0.5
        float u1 = (l1 + gumbel[2 * idx + 1]) * 2.0f;
        float p0 = 1.f / (1.f + expf(u1 - u0));
        float p1 = 1.f / (1.f + expf(u0 - u1));
        s0 += clipf(p0, 1e-7f, 1.f - 1e-7f);
        s1 += clipf(p1, 1e-7f, 1.f - 1e-7f);
    }
    // warp reduce then block reduce
    #pragma unroll
    for (int off = 16; off > 0; off >>= 1) {
        s0 += __shfl_xor_sync(0xffffffffu, s0, off);
        s1 += __shfl_xor_sync(0xffffffffu, s1, off);
    }
    __shared__ float r0[8], r1[8];
    int warp = t >> 5, lane = t & 31;
    if (lane == 0) { r0[warp] = s0; r1[warp] = s1; }
    __syncthreads();
    if (warp == 0) {
        float v0 = (lane < 8) ? r0[lane] : 0.f;
        float v1 = (lane < 8) ? r1[lane] : 0.f;
        #pragma unroll
        for (int off = 4; off > 0; off >>= 1) {
            v0 += __shfl_xor_sync(0xffffffffu, v0, off);
            v1 += __shfl_xor_sync(0xffffffffu, v1, off);
        }
        if (lane == 0) {
            atomicAdd(&g_acc[b],     v0 / (float)NL);
            atomicAdd(&g_acc[8 + b], v1 / (float)NL);
        }
    }
}

// ---------------- launch ----------------
extern "C" void kernel_launch(void* const* d_in, const int* in_sizes, int n_in,
                              void* d_out, int out_size) {
    const float* vt     = (const float*)d_in[0];
    const float* gumbel = (const float*)d_in[1];
    const float* W1     = (const float*)d_in[2];
    const float* b1     = (const float*)d_in[3];
    const float* W2     = (const float*)d_in[4];
    const float* b2     = (const float*)d_in[5];
    const float* W4     = (const float*)d_in[6];
    const float* b4     = (const float*)d_in[7];
    const float* W16    = (const float*)d_in[8];
    const float* b16    = (const float*)d_in[9];
    float* out = (float*)d_out;

    const int SM1  = 2 * (128 + 128) * 128 + 2560;  // 68096 (gemm1)
    const int SMC  = 2 * (64 + 256) * 128 + 1024;   // 82944 (cgemm: 2 stages + bias)
    cudaFuncSetAttribute(gemm1_h, cudaFuncAttributeMaxDynamicSharedMemorySize, SM1);
    cudaFuncSetAttribute(cgemm_h, cudaFuncAttributeMaxDynamicSharedMemorySize, SMC);

    prep_kernel<<<5120, 256>>>(vt, W1, W4, W16);
    gemm1_h<<<dim3(8, 256), 256, SM1>>>(b1, W2);
    router_kernel<<<dim3(8, 8), 256>>>(gumbel, b2);
    cgemm_h<<<dim3(4, 128), 256, SMC>>>(b4, b16, out);
}

// round 17
// speedup vs baseline: 1.0565x; 1.0289x over previous
#include <cuda_runtime.h>
#include <cuda_fp16.h>
#include <cstdint>

#define NB 8
#define NL 4096
#define ND 1024
#define NM1 (NB*NL)      // 32768
#define NM4 (NM1/4)      // 8192
#define NM16 (NM1/16)    // 2048

// ---------------- static device scratch ----------------
__device__ __half g_xh[(size_t)NM1*ND];     // clipped x, fp16 (64 MiB)
__device__ __half g_m4h[(size_t)NM4*ND];    // group-4 means, fp16
__device__ __half g_m16h[(size_t)NM16*ND];  // group-16 means, fp16
__device__ __half g_W1h[(size_t)ND*ND];
__device__ __half g_W4h[(size_t)ND*ND];
__device__ __half g_W16h[(size_t)ND*ND];
__device__ float  g_logitsP[(size_t)8*NM1*2];  // per-nb logit slabs (2 MiB)
__device__ float  g_acc[16];                // [0..7]=mean p4 per batch, [8..15]=mean p16
__device__ int    g_rdone;                  // router-role completion counter

__device__ __forceinline__ float clipf(float v, float lo, float hi) {
    return fminf(fmaxf(v, lo), hi);
}
__device__ __forceinline__ uint32_t smem_u32(const void* p) {
    return (uint32_t)__cvta_generic_to_shared(p);
}

// ---------------- prep: clip + fp16 copy + m4/m16 means + weight conversion ----------------
// blocks [0,2048): token prep ; blocks [2048,5120): W1/W4/W16 -> fp16 (+ g_acc/g_rdone zero)
__global__ void prep_kernel(const float* __restrict__ vt, const float* __restrict__ W1,
                            const float* __restrict__ W4, const float* __restrict__ W16) {
    int t = threadIdx.x;         // 0..255
    if (blockIdx.x >= 2048) {
        int id = (blockIdx.x - 2048) * 256 + t;   // 0..786431, one float4 each
        if (id < 16) g_acc[id] = 0.f;
        if (id == 16) g_rdone = 0;
        int s = id >> 18;
        int j = (id & 262143) << 2;
        const float* src = (s == 0) ? W1 : (s == 1) ? W4 : W16;
        __half* dst = (s == 0) ? g_W1h : (s == 1) ? g_W4h : g_W16h;
        float4 v = *(const float4*)(src + j);
        __half2* hp = (__half2*)(dst + j);
        hp[0] = __floats2half2_rn(v.x, v.y);
        hp[1] = __floats2half2_rn(v.z, v.w);
        return;
    }
    int g = blockIdx.x;          // 0..2047 (16 tokens each)
    int d = t * 4;
    size_t base = (size_t)g * 16 * ND;
    float sx4 = 0.f, sy4 = 0.f, sz4 = 0.f, sw4 = 0.f;
    float sx16 = 0.f, sy16 = 0.f, sz16 = 0.f, sw16 = 0.f;
    #pragma unroll
    for (int r = 0; r < 16; r++) {
        float4 v = *(const float4*)(vt + base + (size_t)r * ND + d);
        v.x = clipf(v.x, -4.f, 4.f);
        v.y = clipf(v.y, -4.f, 4.f);
        v.z = clipf(v.z, -4.f, 4.f);
        v.w = clipf(v.w, -4.f, 4.f);
        __half2* hp = (__half2*)(g_xh + base + (size_t)r * ND + d);
        hp[0] = __floats2half2_rn(v.x, v.y);
        hp[1] = __floats2half2_rn(v.z, v.w);
        sx4 += v.x; sy4 += v.y; sz4 += v.z; sw4 += v.w;
        if ((r & 3) == 3) {
            int r4 = g * 4 + (r >> 2);
            __half2* mp = (__half2*)(g_m4h + (size_t)r4 * ND + d);
            mp[0] = __floats2half2_rn(sx4 * 0.25f, sy4 * 0.25f);
            mp[1] = __floats2half2_rn(sz4 * 0.25f, sw4 * 0.25f);
            sx16 += sx4; sy16 += sy4; sz16 += sz4; sw16 += sw4;
            sx4 = sy4 = sz4 = sw4 = 0.f;
        }
    }
    const float i16 = 1.f / 16.f;
    __half2* mp = (__half2*)(g_m16h + (size_t)g * ND + d);
    mp[0] = __floats2half2_rn(sx16 * i16, sy16 * i16);
    mp[1] = __floats2half2_rn(sz16 * i16, sw16 * i16);
}

// ---------------- GEMM1: fp16, f16 acc, CTA 128x128, BK=64, 2-stage, 3 CTA/SM ----------
// per-nb logit slabs: g_logitsP[nb][row][2] = partial relu(x@W1^T+b1)@W2^T (plain stores)
__global__ void __launch_bounds__(256, 3) gemm1_h(
    const float* __restrict__ pb, const float* __restrict__ pw2)
{
    // PDL: signal early so the dependent cgemm kernel can dispatch into draining slots.
    cudaTriggerProgrammaticLaunchCompletion();

    constexpr int BM  = 128;
    constexpr int STG = (BM + 128) * 128;    // 32768 B per stage (128B rows)
    constexpr int NK  = 16;                  // 1024 / 64

    extern __shared__ __align__(128) char smem[];
    uint32_t sb = smem_u32(smem);
    float* s_b   = (float*)(smem + 2 * STG);
    float* s_w2a = (float*)(smem + 2 * STG + 512);
    float* s_w2b = (float*)(smem + 2 * STG + 1024);

    int tid = threadIdx.x, warp = tid >> 5, lane = tid & 31;
    int wm = warp >> 1, wn = warp & 1;       // 4 x 2 warps, warp tile 32x64
    int mb = blockIdx.y, nb = blockIdx.x;    // mb 0..255, nb 0..7

    if (tid < 128) {
        s_b[tid]   = pb[nb * 128 + tid];
        s_w2a[tid] = pw2[nb * 128 + tid];
        s_w2b[tid] = pw2[ND + nb * 128 + tid];
    }

    const char* Ab = (const char*)g_xh  + (size_t)mb * BM * 2048;
    const char* Bb = (const char*)g_W1h + (size_t)nb * 128 * 2048;

    auto load_stage = [&](int st, int k) {
        uint32_t base = sb + st * STG;
        #pragma unroll
        for (int i = 0; i < 8; i++) {        // 256 rows * 8 chunks = 2048 / 256 thr
            int id = tid + i * 256;
            int row = id >> 3, c = id & 7;
            const char* src = (row < BM)
                ? Ab + (size_t)row * 2048 + (size_t)k * 128 + c * 16
                : Bb + (size_t)(row - BM) * 2048 + (size_t)k * 128 + c * 16;
            uint32_t dst = base + row * 128 + ((c ^ (row & 7)) << 4);
            asm volatile("cp.async.cg.shared.global [%0], [%1], 16;" :: "r"(dst), "l"(src));
        }
        asm volatile("cp.async.commit_group;" ::: "memory");
    };

    uint32_t acch[2][8][2];
    #pragma unroll
    for (int mi = 0; mi < 2; mi++)
        #pragma unroll
        for (int j = 0; j < 8; j++) { acch[mi][j][0] = 0u; acch[mi][j][1] = 0u; }

    // precomputed per-thread ldmatrix row offsets
    int rA[2], sA7[2];
    #pragma unroll
    for (int mi = 0; mi < 2; mi++) {
        int row = wm * 32 + mi * 16 + (lane & 7) + ((lane >> 3) & 1) * 8;
        rA[mi] = row * 128; sA7[mi] = row & 7;
    }
    int rB[4], sB7[4];
    #pragma unroll
    for (int jp = 0; jp < 4; jp++) {
        int row = wn * 64 + (jp * 2 + (lane >> 4)) * 8 + (lane & 7);
        rB[jp] = row * 128; sB7[jp] = row & 7;
    }
    int kA = (lane >> 4);          // A kc low bit
    int kB = ((lane >> 3) & 1);    // B kc low bit

    load_stage(0, 0);

    uint32_t afr[2][2][4], bfr[2][4];

    for (int k = 0; k < NK; k++) {
        asm volatile("cp.async.wait_group 0;" ::: "memory");
        __syncthreads();
        if (k + 1 < NK) load_stage((k + 1) & 1, k + 1);

        uint32_t pA = sb + (k & 1) * STG;
        uint32_t pB = pA + BM * 128;

        auto lda = [&](int ks, uint32_t fr[2][4]) {
            #pragma unroll
            for (int mi = 0; mi < 2; mi++) {
                uint32_t addr = pA + rA[mi] + (((ks * 2 + kA) ^ sA7[mi]) << 4);
                asm volatile("ldmatrix.sync.aligned.m8n8.x4.shared.b16 {%0,%1,%2,%3},[%4];"
                    : "=r"(fr[mi][0]), "=r"(fr[mi][1]), "=r"(fr[mi][2]), "=r"(fr[mi][3])
                    : "r"(addr));
            }
        };
        auto ldb = [&](int ks, int jp, uint32_t fr[4]) {
            uint32_t addr = pB + rB[jp] + (((ks * 2 + kB) ^ sB7[jp]) << 4);
            asm volatile("ldmatrix.sync.aligned.m8n8.x4.shared.b16 {%0,%1,%2,%3},[%4];"
                : "=r"(fr[0]), "=r"(fr[1]), "=r"(fr[2]), "=r"(fr[3])
                : "r"(addr));
        };

        lda(0, afr[0]);
        ldb(0, 0, bfr[0]);
        #pragma unroll
        for (int ks = 0; ks < 4; ks++) {
            if (ks < 3) lda(ks + 1, afr[(ks + 1) & 1]);
            #pragma unroll
            for (int jp = 0; jp < 4; jp++) {
                if (jp < 3)      ldb(ks, jp + 1, bfr[(jp + 1) & 1]);
                else if (ks < 3) ldb(ks + 1, 0, bfr[0]);
                uint32_t* bf = bfr[jp & 1];
                #pragma unroll
                for (int mi = 0; mi < 2; mi++) {
                    uint32_t* af = afr[ks & 1][mi];
                    asm volatile(
                        "mma.sync.aligned.m16n8k16.row.col.f16.f16.f16.f16 "
                        "{%0,%1},{%2,%3,%4,%5},{%6,%7},{%0,%1};"
                        : "+r"(acch[mi][jp * 2][0]), "+r"(acch[mi][jp * 2][1])
                        : "r"(af[0]), "r"(af[1]), "r"(af[2]), "r"(af[3]),
                          "r"(bf[0]), "r"(bf[1]));
                    asm volatile(
                        "mma.sync.aligned.m16n8k16.row.col.f16.f16.f16.f16 "
                        "{%0,%1},{%2,%3,%4,%5},{%6,%7},{%0,%1};"
                        : "+r"(acch[mi][jp * 2 + 1][0]), "+r"(acch[mi][jp * 2 + 1][1])
                        : "r"(af[0]), "r"(af[1]), "r"(af[2]), "r"(af[3]),
                          "r"(bf[2]), "r"(bf[3]));
                }
            }
        }
    }

    // epilogue: h = relu(acc + b1); partial dot with W2; plain stores to per-nb slab
    #pragma unroll
    for (int mi = 0; mi < 2; mi++) {
        float s[2][2] = {{0.f, 0.f}, {0.f, 0.f}};
        #pragma unroll
        for (int j = 0; j < 8; j++) {
            int colb = wn * 64 + j * 8 + (lane & 3) * 2;
            float2 v0 = __half22float2(*(__half2*)&acch[mi][j][0]);
            float2 v1 = __half22float2(*(__half2*)&acch[mi][j][1]);
            float h00 = fmaxf(v0.x + s_b[colb],     0.f);
            float h01 = fmaxf(v0.y + s_b[colb + 1], 0.f);
            float h10 = fmaxf(v1.x + s_b[colb],     0.f);
            float h11 = fmaxf(v1.y + s_b[colb + 1], 0.f);
            s[0][0] += h00 * s_w2a[colb] + h01 * s_w2a[colb + 1];
            s[0][1] += h00 * s_w2b[colb] + h01 * s_w2b[colb + 1];
            s[1][0] += h10 * s_w2a[colb] + h11 * s_w2a[colb + 1];
            s[1][1] += h10 * s_w2b[colb] + h11 * s_w2b[colb + 1];
        }
        #pragma unroll
        for (int off = 1; off < 4; off <<= 1)
            #pragma unroll
            for (int hh = 0; hh < 2; hh++) {
                s[hh][0] += __shfl_xor_sync(0xffffffffu, s[hh][0], off);
                s[hh][1] += __shfl_xor_sync(0xffffffffu, s[hh][1], off);
            }
        // combine the two wn column-halves through smem, wn==1 stores to gmem
        __syncthreads();
        float* s_red = (float*)(smem + 2 * STG + 1536);  // 128 rows * 2 floats
        if (wn == 0 && (lane & 3) == 0) {
            #pragma unroll
            for (int hh = 0; hh < 2; hh++) {
                int rloc = wm * 32 + mi * 16 + hh * 8 + (lane >> 2);
                s_red[2 * rloc]     = s[hh][0];
                s_red[2 * rloc + 1] = s[hh][1];
            }
        }
        __syncthreads();
        if (wn == 1 && (lane & 3) == 0) {
            #pragma unroll
            for (int hh = 0; hh < 2; hh++) {
                int rloc = wm * 32 + mi * 16 + hh * 8 + (lane >> 2);
                int row = mb * BM + rloc;
                float2 o = {s[hh][0] + s_red[2 * rloc], s[hh][1] + s_red[2 * rloc + 1]};
                *(float2*)&g_logitsP[((size_t)nb * NM1 + row) * 2] = o;
            }
        }
    }
}

// ---------------- cgemm + router (PDL secondary of gemm1) ----------------
// blockIdx 0..63: router role — GridDependencySynchronize (full gemm1), gumbel-softmax
//                 reduction -> g_acc, then release g_rdone.
// blockIdx 64..575: tile role — K-loop(s) on prep outputs (no gemm1 dependency),
//                 wait g_rdone before epilogue. Fused tiles (mb<32): c4 write then c16 RMW.
__global__ void __launch_bounds__(256, 2) cgemm_h(
    const float* __restrict__ pb4, const float* __restrict__ pb16, float* __restrict__ outp,
    const float* __restrict__ gumbel, const float* __restrict__ b2)
{
    int tid = threadIdx.x;

    if (blockIdx.x < 64) {
        // ---------- router role ----------
        int b = blockIdx.x >> 3;   // batch
        int sp = blockIdx.x & 7;   // split
        float b20 = __ldg(b2), b21 = __ldg(b2 + 1);
        cudaGridDependencySynchronize();   // wait for gemm1 to fully complete
        float s0 = 0.f, s1 = 0.f;
        #pragma unroll 2
        for (int q = 0; q < 2; q++) {
            int tk = sp * 512 + q * 256 + tid;
            int idx = b * NL + tk;
            float a0 = 0.f, a1 = 0.f;
            #pragma unroll
            for (int nb = 0; nb < 8; nb++) {
                float2 v = *(const float2*)&g_logitsP[((size_t)nb * NM1 + idx) * 2];
                a0 += v.x; a1 += v.y;
            }
            float l0 = clipf(a0 + b20, -15.f, 15.f);
            float l1 = clipf(a1 + b21, -15.f, 15.f);
            float u0 = (l0 + gumbel[2 * idx])     * 2.0f;   // /TEMP, TEMP=0.5
            float u1 = (l1 + gumbel[2 * idx + 1]) * 2.0f;
            float p0 = 1.f / (1.f + expf(u1 - u0));
            float p1 = 1.f / (1.f + expf(u0 - u1));
            s0 += clipf(p0, 1e-7f, 1.f - 1e-7f);
            s1 += clipf(p1, 1e-7f, 1.f - 1e-7f);
        }
        #pragma unroll
        for (int off = 16; off > 0; off >>= 1) {
            s0 += __shfl_xor_sync(0xffffffffu, s0, off);
            s1 += __shfl_xor_sync(0xffffffffu, s1, off);
        }
        __shared__ float r0[8], r1[8];
        int warp = tid >> 5, lane = tid & 31;
        if (lane == 0) { r0[warp] = s0; r1[warp] = s1; }
        __syncthreads();
        if (warp == 0) {
            float v0 = (lane < 8) ? r0[lane] : 0.f;
            float v1 = (lane < 8) ? r1[lane] : 0.f;
            #pragma unroll
            for (int off = 4; off > 0; off >>= 1) {
                v0 += __shfl_xor_sync(0xffffffffu, v0, off);
                v1 += __shfl_xor_sync(0xffffffffu, v1, off);
            }
            if (lane == 0) {
                atomicAdd(&g_acc[b],     v0 / (float)NL);
                atomicAdd(&g_acc[8 + b], v1 / (float)NL);
                __threadfence();
                atomicAdd(&g_rdone, 1);
            }
        }
        return;
    }

    // ---------- tile role ----------
    constexpr int BM  = 64;
    constexpr int STG = (BM + 256) * 128;    // 40960 B per stage (128B rows)
    constexpr int NK  = 16;                  // 1024 / 64

    extern __shared__ __align__(128) char smem[];
    uint32_t sb = smem_u32(smem);
    float* s_b = (float*)(smem + 2 * STG);

    int warp = tid >> 5, lane = tid & 31;
    int wm = warp >> 2, wn = warp & 3;       // 2 x 4; warp tile 32x64
    int tno = blockIdx.x - 64;
    int mb = tno >> 2, nb = tno & 3;

    bool fused = (mb < 32);
    int bb, l0;
    if (fused) { bb = mb >> 2;      l0 = (mb & 3) * 64; }
    else       { int c = mb - 32;   bb = c / 12; l0 = ((c % 12) + 4) * 64; }
    size_t outrow0 = (size_t)bb * 1024 + l0;
    int nph = fused ? 2 : 1;

    float a0 = 0.f, a1 = 0.f, inv = 1.f;     // filled after g_rdone wait

    // per-thread ldmatrix row offsets (phase-invariant)
    int rA[2], sA7[2];
    #pragma unroll
    for (int mi = 0; mi < 2; mi++) {
        int row = wm * 32 + mi * 16 + (lane & 7) + ((lane >> 3) & 1) * 8;
        rA[mi] = row * 128; sA7[mi] = row & 7;
    }
    int rB[4], sB7[4];
    #pragma unroll
    for (int jp = 0; jp < 4; jp++) {
        int row = wn * 64 + (jp * 2 + (lane >> 4)) * 8 + (lane & 7);
        rB[jp] = row * 128; sB7[jp] = row & 7;
    }
    int kA = (lane >> 4);
    int kB = ((lane >> 3) & 1);

    for (int p = 0; p < nph; p++) {
        const char* Ab = p
            ? (const char*)(g_m16h + ((size_t)bb * 256 + l0) * ND)
            : (const char*)(g_m4h  + outrow0 * ND);
        const char* Bb = (p ? (const char*)g_W16h : (const char*)g_W4h) + (size_t)nb * 256 * 2048;
        const float* bias = p ? pb16 : pb4;

        __syncthreads();                     // protect s_b reuse across phases
        if (tid < 256) s_b[tid] = bias[nb * 256 + tid];

        auto load_stage = [&](int st, int k) {
            uint32_t base = sb + st * STG;
            #pragma unroll
            for (int i = 0; i < 10; i++) {   // 320 rows * 8 chunks = 2560 / 256 thr
                int id = tid + i * 256;
                int row = id >> 3, c = id & 7;
                const char* src = (row < BM)
                    ? Ab + (size_t)row * 2048 + (size_t)k * 128 + c * 16
                    : Bb + (size_t)(row - BM) * 2048 + (size_t)k * 128 + c * 16;
                uint32_t dst = base + row * 128 + ((c ^ (row & 7)) << 4);
                asm volatile("cp.async.cg.shared.global [%0], [%1], 16;" :: "r"(dst), "l"(src));
            }
            asm volatile("cp.async.commit_group;" ::: "memory");
        };

        float accf[2][8][4];
        #pragma unroll
        for (int mi = 0; mi < 2; mi++)
            #pragma unroll
            for (int j = 0; j < 8; j++)
                #pragma unroll
                for (int q = 0; q < 4; q++) accf[mi][j][q] = 0.f;

        load_stage(0, 0);

        uint32_t afr[2][2][4], bfr[2][4];

        for (int k = 0; k < NK; k++) {
            asm volatile("cp.async.wait_group 0;" ::: "memory");
            __syncthreads();
            if (k + 1 < NK) load_stage((k + 1) & 1, k + 1);

            uint32_t pA = sb + (k & 1) * STG;
            uint32_t pB = pA + BM * 128;

            auto lda = [&](int ks, uint32_t fr[2][4]) {
                #pragma unroll
                for (int mi = 0; mi < 2; mi++) {
                    uint32_t addr = pA + rA[mi] + (((ks * 2 + kA) ^ sA7[mi]) << 4);
                    asm volatile("ldmatrix.sync.aligned.m8n8.x4.shared.b16 {%0,%1,%2,%3},[%4];"
                        : "=r"(fr[mi][0]), "=r"(fr[mi][1]), "=r"(fr[mi][2]), "=r"(fr[mi][3])
                        : "r"(addr));
                }
            };
            auto ldb = [&](int ks, int jp, uint32_t fr[4]) {
                uint32_t addr = pB + rB[jp] + (((ks * 2 + kB) ^ sB7[jp]) << 4);
                asm volatile("ldmatrix.sync.aligned.m8n8.x4.shared.b16 {%0,%1,%2,%3},[%4];"
                    : "=r"(fr[0]), "=r"(fr[1]), "=r"(fr[2]), "=r"(fr[3])
                    : "r"(addr));
            };

            lda(0, afr[0]);
            ldb(0, 0, bfr[0]);
            #pragma unroll
            for (int ks = 0; ks < 4; ks++) {
                if (ks < 3) lda(ks + 1, afr[(ks + 1) & 1]);
                #pragma unroll
                for (int jp = 0; jp < 4; jp++) {
                    if (jp < 3)      ldb(ks, jp + 1, bfr[(jp + 1) & 1]);
                    else if (ks < 3) ldb(ks + 1, 0, bfr[0]);
                    uint32_t* bf = bfr[jp & 1];
                    #pragma unroll
                    for (int mi = 0; mi < 2; mi++) {
                        uint32_t* af = afr[ks & 1][mi];
                        asm volatile(
                            "mma.sync.aligned.m16n8k16.row.col.f32.f16.f16.f32 "
                            "{%0,%1,%2,%3},{%4,%5,%6,%7},{%8,%9},{%0,%1,%2,%3};"
                            : "+f"(accf[mi][jp * 2][0]), "+f"(accf[mi][jp * 2][1]),
                              "+f"(accf[mi][jp * 2][2]), "+f"(accf[mi][jp * 2][3])
                            : "r"(af[0]), "r"(af[1]), "r"(af[2]), "r"(af[3]),
                              "r"(bf[0]), "r"(bf[1]));
                        asm volatile(
                            "mma.sync.aligned.m16n8k16.row.col.f32.f16.f16.f32 "
                            "{%0,%1,%2,%3},{%4,%5,%6,%7},{%8,%9},{%0,%1,%2,%3};"
                            : "+f"(accf[mi][jp * 2 + 1][0]), "+f"(accf[mi][jp * 2 + 1][1]),
                              "+f"(accf[mi][jp * 2 + 1][2]), "+f"(accf[mi][jp * 2 + 1][3])
                            : "r"(af[0]), "r"(af[1]), "r"(af[2]), "r"(af[3]),
                              "r"(bf[2]), "r"(bf[3]));
                    }
                }
            }
        }

        if (p == 0) {
            // acquire mix weights: wait for all 64 router roles
            if (tid == 0) {
                while (atomicAdd(&g_rdone, 0) < 64) { }
                __threadfence();
            }
            __syncthreads();
            a0 = __ldcg(&g_acc[bb]);
            a1 = __ldcg(&g_acc[8 + bb]);
            inv = 1.f / (a0 + a1 + 1e-7f);
        }
        float amix = (p ? a1 : a0) * inv;

        // epilogue: p==0 plain write (c4), p==1 RMW with final clip (c16)
        #pragma unroll
        for (int mi = 0; mi < 2; mi++) {
            #pragma unroll
            for (int hh = 0; hh < 2; hh++) {
                int rloc = wm * 32 + mi * 16 + hh * 8 + (lane >> 2);
                float* obase = outp + (outrow0 + rloc) * ND + nb * 256 + wn * 64;
                #pragma unroll
                for (int j = 0; j < 8; j++) {
                    int cl = wn * 64 + j * 8 + (lane & 3) * 2;
                    float v0 = amix * clipf(accf[mi][j][hh * 2 + 0] + s_b[cl],     -6.f, 6.f);
                    float v1 = amix * clipf(accf[mi][j][hh * 2 + 1] + s_b[cl + 1], -6.f, 6.f);
                    float* op = obase + j * 8 + (lane & 3) * 2;
                    if (p == 0) {
                        float2 o = {v0, v1};
                        *(float2*)op = o;
                    } else {
                        float2 o = *(float2*)op;
                        o.x = clipf(o.x + v0, -6.f, 6.f);
                        o.y = clipf(o.y + v1, -6.f, 6.f);
                        *(float2*)op = o;
                    }
                }
            }
        }
    }
}

// ---------------- launch ----------------
extern "C" void kernel_launch(void* const* d_in, const int* in_sizes, int n_in,
                              void* d_out, int out_size) {
    const float* vt     = (const float*)d_in[0];
    const float* gumbel = (const float*)d_in[1];
    const float* W1     = (const float*)d_in[2];
    const float* b1     = (const float*)d_in[3];
    const float* W2     = (const float*)d_in[4];
    const float* b2     = (const float*)d_in[5];
    const float* W4     = (const float*)d_in[6];
    const float* b4     = (const float*)d_in[7];
    const float* W16    = (const float*)d_in[8];
    const float* b16    = (const float*)d_in[9];
    float* out = (float*)d_out;

    const int SM1  = 2 * (128 + 128) * 128 + 2560;  // 68096 (gemm1)
    const int SMC  = 2 * (64 + 256) * 128 + 1024;   // 82944 (cgemm)
    cudaFuncSetAttribute(gemm1_h, cudaFuncAttributeMaxDynamicSharedMemorySize, SM1);
    cudaFuncSetAttribute(cgemm_h, cudaFuncAttributeMaxDynamicSharedMemorySize, SMC);

    prep_kernel<<<5120, 256>>>(vt, W1, W4, W16);
    gemm1_h<<<dim3(8, 256), 256, SM1>>>(b1, W2);

    // cgemm launched as PDL secondary: its CTAs may dispatch into gemm1's draining slots.
    cudaLaunchConfig_t cfg = {};
    cfg.gridDim = dim3(576, 1, 1);
    cfg.blockDim = dim3(256, 1, 1);
    cfg.dynamicSmemBytes = SMC;
    cfg.stream = 0;
    cudaLaunchAttribute attrs[1];
    attrs[0].id = cudaLaunchAttributeProgrammaticStreamSerialization;
    attrs[0].val.programmaticStreamSerializationAllowed = 1;
    cfg.attrs = attrs;
    cfg.numAttrs = 1;
    cudaLaunchKernelEx(&cfg, cgemm_h, b4, b16, out, gumbel, b2);
}